// round 6
// baseline (speedup 1.0000x reference)
#include <cuda_runtime.h>
#include <cstdint>

#define MAXN 100352

typedef unsigned long long ull;

__device__ float g_y[MAXN * 64];   // x @ w03 + b03
__device__ float g_hx[MAXN * 16];  // x @ w01[3:] + b01
__device__ float g_blS[4096];      // symmetrized bilinear [(i*16+jj)*16+o]
__device__ float g_c2aQ[192];      // folded q->c2a
__device__ float g_c2aC[64];       // folded const->c2a

// ---- packed f32x2 helpers (FFMA2) ----
__device__ __forceinline__ ull pk2(float lo, float hi) {
    ull r; asm("mov.b64 %0,{%1,%2};" : "=l"(r) : "f"(lo), "f"(hi)); return r;
}
__device__ __forceinline__ ull bc2(float v) { return pk2(v, v); }
__device__ __forceinline__ void upk2(ull v, float& lo, float& hi) {
    asm("mov.b64 {%0,%1},%2;" : "=f"(lo), "=f"(hi) : "l"(v));
}
__device__ __forceinline__ ull fma2_(ull a, ull b, ull c) {
    ull d; asm("fma.rn.f32x2 %0,%1,%2,%3;" : "=l"(d) : "l"(a), "l"(b), "l"(c)); return d;
}
__device__ __forceinline__ ull add2_(ull a, ull b) {
    ull d; asm("add.rn.f32x2 %0,%1,%2;" : "=l"(d) : "l"(a), "l"(b)); return d;
}
__device__ __forceinline__ ull mul2_(ull a, ull b) {
    ull d; asm("mul.rn.f32x2 %0,%1,%2;" : "=l"(d) : "l"(a), "l"(b)); return d;
}

// ---------------------------------------------------------------------------
// Prep kernel: data blocks compute y & hx; 17 tail blocks do weight setup.
// ---------------------------------------------------------------------------
__global__ void __launch_bounds__(256) prep_kernel(
    const float* __restrict__ x, const float* __restrict__ w03,
    const float* __restrict__ b03, const float* __restrict__ w01,
    const float* __restrict__ b01,
    const float* __restrict__ blW, const float* __restrict__ c2aw,
    const float* __restrict__ lp2w, const float* __restrict__ lp2b,
    int n, int nb_data)
{
    const int tid = threadIdx.x;
    if (blockIdx.x >= nb_data) {
        const int sb = blockIdx.x - nb_data;
        if (sb < 16) {
            const int id = sb * 256 + tid;
            const int o = id & 15;
            const int pr = id >> 4;
            const int jj = pr & 15;
            const int i = pr >> 4;
            float v;
            if (i < jj)       v = blW[o * 256 + i * 16 + jj] + blW[o * 256 + jj * 16 + i];
            else if (i == jj) v = blW[o * 256 + i * 16 + i];
            else              v = 0.f;
            g_blS[id] = v;
        } else {
            __shared__ float sM[48], s0[16];
            if (tid < 48) {
                const int r = tid >> 4, u = tid & 15;
                sM[tid] = lp2w[r * 64 + u] + lp2w[r * 64 + 16 + u] +
                          lp2w[r * 64 + 32 + u] + lp2w[r * 64 + 48 + u];
            }
            if (tid >= 48 && tid < 64) {
                const int u = tid - 48;
                s0[u] = lp2b[u] + lp2b[16 + u] + lp2b[32 + u] + lp2b[48 + u];
            }
            __syncthreads();
            if (tid < 192) {
                const int r = tid >> 6, c = tid & 63;
                float acc = 0.f;
#pragma unroll
                for (int u = 0; u < 16; u++)
                    acc += sM[r * 16 + u] * c2aw[(16 + u) * 64 + c];
                g_c2aQ[r * 64 + c] = acc;
            } else {
                const int c = tid - 192;
                float acc = 0.f;
#pragma unroll
                for (int u = 0; u < 16; u++)
                    acc += s0[u] * c2aw[(16 + u) * 64 + c];
                g_c2aC[c] = acc;
            }
        }
        return;
    }

    __shared__ float sw[4096];
    __shared__ float sw1[1024];
    __shared__ float sx[32][64];
    for (int i = tid; i < 1024; i += 256)
        ((float4*)sw)[i] = ((const float4*)w03)[i];
    for (int i = tid; i < 256; i += 256)
        ((float4*)sw1)[i] = ((const float4*)(w01 + 48))[i];
    const int base = blockIdx.x * 32;
    {
        const int c4 = tid & 15;
        const int r = tid >> 4;
#pragma unroll
        for (int a = 0; a < 2; a++) {
            const int row = base + r + a * 16;
            float4 v = make_float4(0.f, 0.f, 0.f, 0.f);
            if (row < n) v = ((const float4*)(x + (size_t)row * 64))[c4];
            ((float4*)sx[r + a * 16])[c4] = v;
        }
    }
    __syncthreads();

    {
        const int rq = tid >> 5;
        const int cp = tid & 31;
        const ull bcp = ((const ull*)b03)[cp];
        ull acc0 = bcp, acc1 = bcp, acc2 = bcp, acc3 = bcp;
#pragma unroll 8
        for (int d = 0; d < 64; d++) {
            const ull w2 = ((const ull*)(sw + d * 64))[cp];
            acc0 = fma2_(bc2(sx[rq * 4 + 0][d]), w2, acc0);
            acc1 = fma2_(bc2(sx[rq * 4 + 1][d]), w2, acc1);
            acc2 = fma2_(bc2(sx[rq * 4 + 2][d]), w2, acc2);
            acc3 = fma2_(bc2(sx[rq * 4 + 3][d]), w2, acc3);
        }
        const int r0 = base + rq * 4;
        if (r0 + 0 < n) ((ull*)(g_y + (size_t)(r0 + 0) * 64))[cp] = acc0;
        if (r0 + 1 < n) ((ull*)(g_y + (size_t)(r0 + 1) * 64))[cp] = acc1;
        if (r0 + 2 < n) ((ull*)(g_y + (size_t)(r0 + 2) * 64))[cp] = acc2;
        if (r0 + 3 < n) ((ull*)(g_y + (size_t)(r0 + 3) * 64))[cp] = acc3;
    }
    {
        const int r = tid >> 3;
        const int o8 = tid & 7;
        ull acc = ((const ull*)b01)[o8];
#pragma unroll 8
        for (int d = 0; d < 64; d++)
            acc = fma2_(bc2(sx[r][d]), ((const ull*)(sw1 + d * 16))[o8], acc);
        const int row = base + r;
        if (row < n) ((ull*)(g_hx + (size_t)row * 16))[o8] = acc;
    }
}

// ---------------------------------------------------------------------------
// Reduce kernel: out[n][c] = sum_k xk[n][k][c]
// ---------------------------------------------------------------------------
__global__ void __launch_bounds__(256) reduce_kernel(
    const float* __restrict__ xk, float* __restrict__ out, int n)
{
    const int idx = blockIdx.x * 256 + threadIdx.x;
    if (idx >= n * 32) return;
    const int nn = idx >> 5;
    const int cp = idx & 31;
    const ull* b = (const ull*)(xk + (size_t)nn * 1024) + cp;
    ull acc = b[0];
#pragma unroll
    for (int kk = 1; kk < 16; kk++) acc = add2_(acc, b[kk * 32]);
    ((ull*)(out + (size_t)nn * 64))[cp] = acc;
}

// ---------------------------------------------------------------------------
// Main kernel: 128 threads, P=4 point-slots per thread (32 points/block).
// ---------------------------------------------------------------------------
__global__ void __launch_bounds__(128, 3) pm_main_kernel(
    const float* __restrict__ p,
    const int* __restrict__ knn,
    const float* __restrict__ w01, const float* __restrict__ blB,
    const float* __restrict__ lp1w, const float* __restrict__ lp1b,
    const float* __restrict__ bnpg, const float* __restrict__ bnpb,
    const float* __restrict__ bnpm, const float* __restrict__ bnpv,
    const float* __restrict__ lp2w, const float* __restrict__ lp2b,
    const float* __restrict__ c2aw,
    const float* __restrict__ bn2ag, const float* __restrict__ bn2ab,
    const float* __restrict__ bn2am, const float* __restrict__ bn2av,
    const float* __restrict__ c2bw,
    const float* __restrict__ bn2bg, const float* __restrict__ bn2bb,
    const float* __restrict__ bn2bm, const float* __restrict__ bn2bv,
    const float* __restrict__ c2cw, const float* __restrict__ c2cb,
    float* __restrict__ out, float* __restrict__ xk_out,
    float* __restrict__ knn_out, float* __restrict__ pr_out,
    int n)
{
    __shared__ __align__(16) float s_blS[4096];
    __shared__ __align__(16) float s_c2a[1024];
    __shared__ __align__(16) float s_c2aQ[192];
    __shared__ __align__(16) float s_c2aC[64];
    __shared__ __align__(16) float s_c2b[512];
    __shared__ __align__(16) float s_c2c[64];
    __shared__ __align__(16) float s_lp2[192], s_lp2b[64];
    __shared__ __align__(16) float s_bn2as[64], s_bn2at[64];
    __shared__ __align__(16) float s_w01p[48];
    __shared__ __align__(16) float s_blB[16];
    __shared__ __align__(16) float s_lp1f[12], s_lp1c[4];
    __shared__ __align__(16) float s_bn2bs[8], s_bn2bt[8], s_c2cb[8];
    __shared__ __align__(16) ull s_escr[128 * 17];   // slot-2/3 energy spill

    const int tid = threadIdx.x;

    // ---- staging ----
#pragma unroll
    for (int i = 0; i < 8; i++)
        ((float4*)s_blS)[tid + i * 128] = ((const float4*)g_blS)[tid + i * 128];
#pragma unroll
    for (int i = 0; i < 2; i++)
        ((float4*)s_c2a)[tid + i * 128] = ((const float4*)c2aw)[tid + i * 128];
    ((float4*)s_c2b)[tid] = ((const float4*)c2bw)[tid];
    for (int i = tid; i < 192; i += 128) { s_c2aQ[i] = g_c2aQ[i]; s_lp2[i] = lp2w[i]; }
    if (tid < 64) {
        s_c2aC[tid] = g_c2aC[tid];
        s_lp2b[tid] = lp2b[tid];
        float sc = bn2ag[tid] * rsqrtf(bn2av[tid] + 1e-5f);
        s_bn2as[tid] = sc;
        s_bn2at[tid] = bn2ab[tid] - bn2am[tid] * sc;
        s_c2c[tid] = c2cw[tid];
    }
    if (tid < 48) s_w01p[tid] = w01[tid];
    if (tid < 16) s_blB[tid] = blB[tid];
    if (tid < 8) {
        float sc = bn2bg[tid] * rsqrtf(bn2bv[tid] + 1e-5f);
        s_bn2bs[tid] = sc;
        s_bn2bt[tid] = bn2bb[tid] - bn2bm[tid] * sc;
        s_c2cb[tid] = c2cb[tid];
    }
    if (tid < 3) {
        const int d = tid;
        float sc = bnpg[d] * rsqrtf(bnpv[d] + 1e-5f);
        s_lp1f[0 + d] = lp1w[0 * 3 + d] * sc;
        s_lp1f[4 + d] = lp1w[1 * 3 + d] * sc;
        s_lp1f[8 + d] = lp1w[2 * 3 + d] * sc;
        s_lp1c[d] = (lp1b[d] - bnpm[d]) * sc + bnpb[d];
    }
    __syncthreads();

    // ---- slot setup: warp = 2 k-halves; each thread 4 consecutive points ----
    const int k = tid & 15;
    const int half = (tid >> 4) & 1;
    const int wrp = tid >> 5;
    const int base = blockIdx.x * 32 + wrp * 8 + half * 4;

    int jS[4]; bool vS[4];
    float pr[4][3];
#pragma unroll
    for (int s = 0; s < 4; s++) {
        const int nn = base + s;
        const bool v = nn < n;
        const int nc = v ? nn : (n > 0 ? n - 1 : 0);
        const int j = knn[(size_t)nc * 16 + k];
        jS[s] = j; vS[s] = v;
        pr[s][0] = p[(size_t)j * 3 + 0] - p[(size_t)nc * 3 + 0];
        pr[s][1] = p[(size_t)j * 3 + 1] - p[(size_t)nc * 3 + 1];
        pr[s][2] = p[(size_t)j * 3 + 2] - p[(size_t)nc * 3 + 2];
        if (v && pr_out) {
            pr_out[((size_t)nn * 16 + k) * 3 + 0] = pr[s][0];
            pr_out[((size_t)nn * 16 + k) * 3 + 1] = pr[s][1];
            pr_out[((size_t)nn * 16 + k) * 3 + 2] = pr[s][2];
        }
        if (v && knn_out) knn_out[(size_t)nn * 16 + k] = (float)j;
    }

    // ---- h = relu(hx[j] + pr @ w01p) ----
    float h[4][16];
#pragma unroll
    for (int o4 = 0; o4 < 4; o4++) {
        float4 w0 = *(const float4*)(s_w01p + o4 * 4);
        float4 w1 = *(const float4*)(s_w01p + 16 + o4 * 4);
        float4 w2 = *(const float4*)(s_w01p + 32 + o4 * 4);
#pragma unroll
        for (int s = 0; s < 4; s++) {
            float4 a = ((const float4*)(g_hx + (size_t)jS[s] * 16))[o4];
            h[s][o4 * 4 + 0] = fmaxf(a.x + pr[s][0] * w0.x + pr[s][1] * w1.x + pr[s][2] * w2.x, 0.f);
            h[s][o4 * 4 + 1] = fmaxf(a.y + pr[s][0] * w0.y + pr[s][1] * w1.y + pr[s][2] * w2.y, 0.f);
            h[s][o4 * 4 + 2] = fmaxf(a.z + pr[s][0] * w0.z + pr[s][1] * w1.z + pr[s][2] * w2.z, 0.f);
            h[s][o4 * 4 + 3] = fmaxf(a.w + pr[s][0] * w0.w + pr[s][1] * w1.w + pr[s][2] * w2.w, 0.f);
        }
    }

    // ---- q = relu(BN(pr @ lp1)) ; pr dead after ----
    float q[4][3];
#pragma unroll
    for (int s = 0; s < 4; s++)
#pragma unroll
        for (int d = 0; d < 3; d++)
            q[s][d] = fmaxf(fmaf(pr[s][0], s_lp1f[d],
                          fmaf(pr[s][1], s_lp1f[4 + d],
                          fmaf(pr[s][2], s_lp1f[8 + d], s_lp1c[d]))), 0.f);

    // ---- symmetrized bilinear, channel-packed ----
    ull ep0[8], ep1[8], ep2[8], ep3[8];
    {
        const ull* bB = (const ull*)s_blB;
#pragma unroll
        for (int m = 0; m < 8; m++) { ull b = bB[m]; ep0[m] = b; ep1[m] = b; ep2[m] = b; ep3[m] = b; }
    }
#pragma unroll
    for (int i = 0; i < 16; i++) {
#pragma unroll
        for (int jj = i; jj < 16; jj++) {
            const ull g0 = bc2(h[0][i] * h[0][jj]);
            const ull g1 = bc2(h[1][i] * h[1][jj]);
            const ull g2 = bc2(h[2][i] * h[2][jj]);
            const ull g3 = bc2(h[3][i] * h[3][jj]);
            const ulonglong2* wr = (const ulonglong2*)(s_blS + (i * 16 + jj) * 16);
            {
                ulonglong2 w0 = wr[0], w1 = wr[1];
                ep0[0] = fma2_(g0, w0.x, ep0[0]); ep0[1] = fma2_(g0, w0.y, ep0[1]);
                ep0[2] = fma2_(g0, w1.x, ep0[2]); ep0[3] = fma2_(g0, w1.y, ep0[3]);
                ep1[0] = fma2_(g1, w0.x, ep1[0]); ep1[1] = fma2_(g1, w0.y, ep1[1]);
                ep1[2] = fma2_(g1, w1.x, ep1[2]); ep1[3] = fma2_(g1, w1.y, ep1[3]);
                ep2[0] = fma2_(g2, w0.x, ep2[0]); ep2[1] = fma2_(g2, w0.y, ep2[1]);
                ep2[2] = fma2_(g2, w1.x, ep2[2]); ep2[3] = fma2_(g2, w1.y, ep2[3]);
                ep3[0] = fma2_(g3, w0.x, ep3[0]); ep3[1] = fma2_(g3, w0.y, ep3[1]);
                ep3[2] = fma2_(g3, w1.x, ep3[2]); ep3[3] = fma2_(g3, w1.y, ep3[3]);
            }
            {
                ulonglong2 w2 = wr[2], w3 = wr[3];
                ep0[4] = fma2_(g0, w2.x, ep0[4]); ep0[5] = fma2_(g0, w2.y, ep0[5]);
                ep0[6] = fma2_(g0, w3.x, ep0[6]); ep0[7] = fma2_(g0, w3.y, ep0[7]);
                ep1[4] = fma2_(g1, w2.x, ep1[4]); ep1[5] = fma2_(g1, w2.y, ep1[5]);
                ep1[6] = fma2_(g1, w3.x, ep1[6]); ep1[7] = fma2_(g1, w3.y, ep1[7]);
                ep2[4] = fma2_(g2, w2.x, ep2[4]); ep2[5] = fma2_(g2, w2.y, ep2[5]);
                ep2[6] = fma2_(g2, w3.x, ep2[6]); ep2[7] = fma2_(g2, w3.y, ep2[7]);
                ep3[4] = fma2_(g3, w2.x, ep3[4]); ep3[5] = fma2_(g3, w2.y, ep3[5]);
                ep3[6] = fma2_(g3, w3.x, ep3[6]); ep3[7] = fma2_(g3, w3.y, ep3[7]);
            }
        }
    }
    // spill slot-2/3 energies to smem scratch (frees 32 regs)
    {
        ull* es = s_escr + tid * 17;
#pragma unroll
        for (int m = 0; m < 8; m++) { es[m] = ep2[m]; es[8 + m] = ep3[m]; }
    }

    // ---- fused c2a(+q)+BN+relu+c2b ----
    ull hb0[4], hb1[4], hb2[4], hb3[4];
#pragma unroll
    for (int m = 0; m < 4; m++) { hb0[m] = 0ull; hb1[m] = 0ull; hb2[m] = 0ull; hb3[m] = 0ull; }
#pragma unroll 1
    for (int cb = 0; cb < 4; cb++) {
        ull a0[8], a1[8], a2[8], a3[8];
        {
            const ulonglong2* ccp = (const ulonglong2*)(s_c2aC + cb * 16);
            ulonglong2 c0 = ccp[0], c1 = ccp[1], c2 = ccp[2], c3 = ccp[3];
            a0[0] = c0.x; a0[1] = c0.y; a0[2] = c1.x; a0[3] = c1.y;
            a0[4] = c2.x; a0[5] = c2.y; a0[6] = c3.x; a0[7] = c3.y;
#pragma unroll
            for (int m = 0; m < 8; m++) { a1[m] = a0[m]; a2[m] = a0[m]; a3[m] = a0[m]; }
        }
        const ull* es = s_escr + tid * 17;
#pragma unroll
        for (int q8 = 0; q8 < 8; q8++) {
            float e0l, e0h, e1l, e1h, e2l, e2h, e3l, e3h;
            upk2(ep0[q8], e0l, e0h);
            upk2(ep1[q8], e1l, e1h);
            upk2(es[q8], e2l, e2h);
            upk2(es[8 + q8], e3l, e3h);
#pragma unroll
            for (int hh = 0; hh < 2; hh++) {
                const ull v0 = bc2(hh ? e0h : e0l);
                const ull v1 = bc2(hh ? e1h : e1l);
                const ull v2 = bc2(hh ? e2h : e2l);
                const ull v3 = bc2(hh ? e3h : e3l);
                const ulonglong2* wr = (const ulonglong2*)(s_c2a + (2 * q8 + hh) * 64 + cb * 16);
                ulonglong2 w0 = wr[0], w1 = wr[1], w2 = wr[2], w3 = wr[3];
                a0[0] = fma2_(v0, w0.x, a0[0]); a0[1] = fma2_(v0, w0.y, a0[1]);
                a0[2] = fma2_(v0, w1.x, a0[2]); a0[3] = fma2_(v0, w1.y, a0[3]);
                a0[4] = fma2_(v0, w2.x, a0[4]); a0[5] = fma2_(v0, w2.y, a0[5]);
                a0[6] = fma2_(v0, w3.x, a0[6]); a0[7] = fma2_(v0, w3.y, a0[7]);
                a1[0] = fma2_(v1, w0.x, a1[0]); a1[1] = fma2_(v1, w0.y, a1[1]);
                a1[2] = fma2_(v1, w1.x, a1[2]); a1[3] = fma2_(v1, w1.y, a1[3]);
                a1[4] = fma2_(v1, w2.x, a1[4]); a1[5] = fma2_(v1, w2.y, a1[5]);
                a1[6] = fma2_(v1, w3.x, a1[6]); a1[7] = fma2_(v1, w3.y, a1[7]);
                a2[0] = fma2_(v2, w0.x, a2[0]); a2[1] = fma2_(v2, w0.y, a2[1]);
                a2[2] = fma2_(v2, w1.x, a2[2]); a2[3] = fma2_(v2, w1.y, a2[3]);
                a2[4] = fma2_(v2, w2.x, a2[4]); a2[5] = fma2_(v2, w2.y, a2[5]);
                a2[6] = fma2_(v2, w3.x, a2[6]); a2[7] = fma2_(v2, w3.y, a2[7]);
                a3[0] = fma2_(v3, w0.x, a3[0]); a3[1] = fma2_(v3, w0.y, a3[1]);
                a3[2] = fma2_(v3, w1.x, a3[2]); a3[3] = fma2_(v3, w1.y, a3[3]);
                a3[4] = fma2_(v3, w2.x, a3[4]); a3[5] = fma2_(v3, w2.y, a3[5]);
                a3[6] = fma2_(v3, w3.x, a3[6]); a3[7] = fma2_(v3, w3.y, a3[7]);
            }
        }
#pragma unroll
        for (int r = 0; r < 3; r++) {
            const ull v0 = bc2(q[0][r]);
            const ull v1 = bc2(q[1][r]);
            const ull v2 = bc2(q[2][r]);
            const ull v3 = bc2(q[3][r]);
            const ulonglong2* wr = (const ulonglong2*)(s_c2aQ + r * 64 + cb * 16);
            ulonglong2 w0 = wr[0], w1 = wr[1], w2 = wr[2], w3 = wr[3];
            a0[0] = fma2_(v0, w0.x, a0[0]); a0[1] = fma2_(v0, w0.y, a0[1]);
            a0[2] = fma2_(v0, w1.x, a0[2]); a0[3] = fma2_(v0, w1.y, a0[3]);
            a0[4] = fma2_(v0, w2.x, a0[4]); a0[5] = fma2_(v0, w2.y, a0[5]);
            a0[6] = fma2_(v0, w3.x, a0[6]); a0[7] = fma2_(v0, w3.y, a0[7]);
            a1[0] = fma2_(v1, w0.x, a1[0]); a1[1] = fma2_(v1, w0.y, a1[1]);
            a1[2] = fma2_(v1, w1.x, a1[2]); a1[3] = fma2_(v1, w1.y, a1[3]);
            a1[4] = fma2_(v1, w2.x, a1[4]); a1[5] = fma2_(v1, w2.y, a1[5]);
            a1[6] = fma2_(v1, w3.x, a1[6]); a1[7] = fma2_(v1, w3.y, a1[7]);
            a2[0] = fma2_(v2, w0.x, a2[0]); a2[1] = fma2_(v2, w0.y, a2[1]);
            a2[2] = fma2_(v2, w1.x, a2[2]); a2[3] = fma2_(v2, w1.y, a2[3]);
            a2[4] = fma2_(v2, w2.x, a2[4]); a2[5] = fma2_(v2, w2.y, a2[5]);
            a2[6] = fma2_(v2, w3.x, a2[6]); a2[7] = fma2_(v2, w3.y, a2[7]);
            a3[0] = fma2_(v3, w0.x, a3[0]); a3[1] = fma2_(v3, w0.y, a3[1]);
            a3[2] = fma2_(v3, w1.x, a3[2]); a3[3] = fma2_(v3, w1.y, a3[3]);
            a3[4] = fma2_(v3, w2.x, a3[4]); a3[5] = fma2_(v3, w2.y, a3[5]);
            a3[6] = fma2_(v3, w3.x, a3[6]); a3[7] = fma2_(v3, w3.y, a3[7]);
        }
        // BN + relu + c2b
        const ull* scp = (const ull*)(s_bn2as + cb * 16);
        const ull* shp = (const ull*)(s_bn2at + cb * 16);
#pragma unroll
        for (int qq = 0; qq < 8; qq++) {
            float sc0, sc1, sh0, sh1;
            upk2(scp[qq], sc0, sc1); upk2(shp[qq], sh0, sh1);
            const ulonglong2* wb0 = (const ulonglong2*)(s_c2b + (cb * 16 + 2 * qq) * 8);
            const ulonglong2* wb1 = (const ulonglong2*)(s_c2b + (cb * 16 + 2 * qq + 1) * 8);
            ulonglong2 u0 = wb0[0], u1 = wb0[1];
            ulonglong2 u2 = wb1[0], u3 = wb1[1];
#pragma unroll
            for (int s = 0; s < 4; s++) {
                const ull av = (s == 0) ? a0[qq] : (s == 1) ? a1[qq] : (s == 2) ? a2[qq] : a3[qq];
                ull* hb = (s == 0) ? hb0 : (s == 1) ? hb1 : (s == 2) ? hb2 : hb3;
                float vlo, vhi;
                upk2(av, vlo, vhi);
                vlo = fmaxf(fmaf(vlo, sc0, sh0), 0.f);
                vhi = fmaxf(fmaf(vhi, sc1, sh1), 0.f);
                const ull bl = bc2(vlo), bh = bc2(vhi);
                hb[0] = fma2_(bl, u0.x, hb[0]); hb[1] = fma2_(bl, u0.y, hb[1]);
                hb[2] = fma2_(bl, u1.x, hb[2]); hb[3] = fma2_(bl, u1.y, hb[3]);
                hb[0] = fma2_(bh, u2.x, hb[0]); hb[1] = fma2_(bh, u2.y, hb[1]);
                hb[2] = fma2_(bh, u3.x, hb[2]); hb[3] = fma2_(bh, u3.y, hb[3]);
            }
        }
    }

    // ---- BN2b + relu, logits, softmax (no max pass; |logits| << 1) ----
    ull wsp[4][4];
#pragma unroll
    for (int s = 0; s < 4; s++) {
        const ull* hbp = (s == 0) ? hb0 : (s == 1) ? hb1 : (s == 2) ? hb2 : hb3;
        float hbs[8];
#pragma unroll
        for (int m = 0; m < 4; m++) upk2(hbp[m], hbs[2 * m], hbs[2 * m + 1]);
#pragma unroll
        for (int u = 0; u < 8; u++)
            hbs[u] = fmaxf(fmaf(hbs[u], s_bn2bs[u], s_bn2bt[u]), 0.f);

        ull lgp[4];
        {
            const ull* cbp = (const ull*)s_c2cb;
#pragma unroll
            for (int m = 0; m < 4; m++) lgp[m] = cbp[m];
        }
#pragma unroll
        for (int u = 0; u < 8; u++) {
            const ull hv = bc2(hbs[u]);
            const ulonglong2* wr = (const ulonglong2*)(s_c2c + u * 8);
            ulonglong2 w0 = wr[0], w1 = wr[1];
            lgp[0] = fma2_(hv, w0.x, lgp[0]); lgp[1] = fma2_(hv, w0.y, lgp[1]);
            lgp[2] = fma2_(hv, w1.x, lgp[2]); lgp[3] = fma2_(hv, w1.y, lgp[3]);
        }
        float ws[8];
#pragma unroll
        for (int m = 0; m < 4; m++) {
            float l0, l1;
            upk2(lgp[m], l0, l1);
            ws[2 * m] = __expf(l0);
            ws[2 * m + 1] = __expf(l1);
        }
#pragma unroll
        for (int c = 0; c < 8; c++) {
            float sm = ws[c];
#pragma unroll
            for (int d = 8; d > 0; d >>= 1)
                sm += __shfl_xor_sync(0xffffffffu, sm, d);
            ws[c] = __fdividef(ws[c], sm);
        }
#pragma unroll
        for (int m = 0; m < 4; m++) wsp[s][m] = pk2(ws[2 * m], ws[2 * m + 1]);
    }

    // ---- epilogue: xk = (y + pe) * w ; out via reduce kernel (or tree) ----
    {
        const bool do_tree = (xk_out == nullptr);
        ull qp[4][3];
#pragma unroll
        for (int s = 0; s < 4; s++)
#pragma unroll
            for (int d = 0; d < 3; d++) qp[s][d] = bc2(q[s][d]);
#pragma unroll
        for (int c4 = 0; c4 < 16; c4++) {
            ulonglong2 l0 = ((const ulonglong2*)s_lp2)[c4];
            ulonglong2 l1 = ((const ulonglong2*)(s_lp2 + 64))[c4];
            ulonglong2 l2 = ((const ulonglong2*)(s_lp2 + 128))[c4];
            ulonglong2 lb = ((const ulonglong2*)s_lp2b)[c4];
#pragma unroll
            for (int s = 0; s < 4; s++) {
                ulonglong2 y = ((const ulonglong2*)(g_y + (size_t)jS[s] * 64))[c4];
                ull pe = fma2_(qp[s][0], l0.x, fma2_(qp[s][1], l1.x, fma2_(qp[s][2], l2.x, lb.x)));
                ull vx = mul2_(add2_(y.x, pe), wsp[s][(2 * c4) & 3]);
                pe = fma2_(qp[s][0], l0.y, fma2_(qp[s][1], l1.y, fma2_(qp[s][2], l2.y, lb.y)));
                ull vy = mul2_(add2_(y.y, pe), wsp[s][(2 * c4 + 1) & 3]);
                if (!do_tree) {
                    if (vS[s]) {
                        ulonglong2 t; t.x = vx; t.y = vy;
                        ((ulonglong2*)(xk_out + ((size_t)(base + s) * 16 + k) * 64))[c4] = t;
                    }
                } else {
#pragma unroll
                    for (int d = 8; d > 0; d >>= 1) {
                        vx = add2_(vx, __shfl_down_sync(0xffffffffu, vx, d, 16));
                        vy = add2_(vy, __shfl_down_sync(0xffffffffu, vy, d, 16));
                    }
                    if (k == 0 && vS[s]) {
                        ulonglong2 t; t.x = vx; t.y = vy;
                        ((ulonglong2*)(out + (size_t)(base + s) * 64))[c4] = t;
                    }
                }
            }
        }
    }
}

// ---------------------------------------------------------------------------
extern "C" void kernel_launch(void* const* d_in, const int* in_sizes, int n_in,
                              void* d_out, int out_size)
{
    const float* p    = (const float*)d_in[0];
    const float* x    = (const float*)d_in[1];
    const int*   knn  = (const int*)d_in[2];
    const float* w01  = (const float*)d_in[3];
    const float* b01  = (const float*)d_in[4];
    const float* blW  = (const float*)d_in[5];
    const float* blB  = (const float*)d_in[6];
    const float* lp1w = (const float*)d_in[7];
    const float* lp1b = (const float*)d_in[8];
    const float* bnpg = (const float*)d_in[9];
    const float* bnpb = (const float*)d_in[10];
    const float* bnpm = (const float*)d_in[11];
    const float* bnpv = (const float*)d_in[12];
    const float* lp2w = (const float*)d_in[13];
    const float* lp2b = (const float*)d_in[14];
    const float* c2aw = (const float*)d_in[15];
    const float* bn2ag = (const float*)d_in[16];
    const float* bn2ab = (const float*)d_in[17];
    const float* bn2am = (const float*)d_in[18];
    const float* bn2av = (const float*)d_in[19];
    const float* c2bw  = (const float*)d_in[20];
    const float* bn2bg = (const float*)d_in[21];
    const float* bn2bb = (const float*)d_in[22];
    const float* bn2bm = (const float*)d_in[23];
    const float* bn2bv = (const float*)d_in[24];
    const float* c2cw  = (const float*)d_in[25];
    const float* c2cb  = (const float*)d_in[26];
    const float* w03   = (const float*)d_in[27];
    const float* b03   = (const float*)d_in[28];

    const int n = in_sizes[0] / 3;
    float* out = (float*)d_out;

    const long long total = (long long)n * 64 + (long long)n * 16 * 64 +
                            (long long)n * 16 + (long long)n * 16 * 3;
    float* xk_out = nullptr;
    float* knn_out = nullptr;
    float* pr_out = nullptr;
    if ((long long)out_size >= total) {
        xk_out  = out + (size_t)n * 64;
        knn_out = xk_out + (size_t)n * 16 * 64;
        pr_out  = knn_out + (size_t)n * 16;
    }

    const int nb_data = (n + 31) / 32;
    prep_kernel<<<nb_data + 17, 256>>>(x, w03, b03, w01, b01,
                                       blW, c2aw, lp2w, lp2b, n, nb_data);
    pm_main_kernel<<<(n + 31) / 32, 128>>>(p, knn, w01, blB,
                               lp1w, lp1b, bnpg, bnpb, bnpm, bnpv, lp2w, lp2b,
                               c2aw, bn2ag, bn2ab, bn2am, bn2av,
                               c2bw, bn2bg, bn2bb, bn2bm, bn2bv,
                               c2cw, c2cb,
                               out, xk_out, knn_out, pr_out, n);
    if (xk_out)
        reduce_kernel<<<(n * 32 + 255) / 256, 256>>>(xk_out, out, n);
}

// round 7
// speedup vs baseline: 1.5682x; 1.5682x over previous
#include <cuda_runtime.h>
#include <cstdint>

#define MAXN 100352

typedef unsigned long long ull;

__device__ float g_y[MAXN * 64];   // x @ w03 + b03
__device__ float g_hx[MAXN * 16];  // x @ w01[3:] + b01
__device__ float g_blS[4096];      // symmetrized bilinear [(i*16+jj)*16+o]
__device__ float g_c2aQ[192];      // folded q->c2a
__device__ float g_c2aC[64];       // folded const->c2a

// ---- packed f32x2 helpers (FFMA2) ----
__device__ __forceinline__ ull pk2(float lo, float hi) {
    ull r; asm("mov.b64 %0,{%1,%2};" : "=l"(r) : "f"(lo), "f"(hi)); return r;
}
__device__ __forceinline__ ull bc2(float v) { return pk2(v, v); }
__device__ __forceinline__ void upk2(ull v, float& lo, float& hi) {
    asm("mov.b64 {%0,%1},%2;" : "=f"(lo), "=f"(hi) : "l"(v));
}
__device__ __forceinline__ ull fma2_(ull a, ull b, ull c) {
    ull d; asm("fma.rn.f32x2 %0,%1,%2,%3;" : "=l"(d) : "l"(a), "l"(b), "l"(c)); return d;
}
__device__ __forceinline__ ull add2_(ull a, ull b) {
    ull d; asm("add.rn.f32x2 %0,%1,%2;" : "=l"(d) : "l"(a), "l"(b)); return d;
}
__device__ __forceinline__ ull mul2_(ull a, ull b) {
    ull d; asm("mul.rn.f32x2 %0,%1,%2;" : "=l"(d) : "l"(a), "l"(b)); return d;
}

// ---------------------------------------------------------------------------
// Prep kernel: data blocks compute y & hx; 17 tail blocks do weight setup.
// ---------------------------------------------------------------------------
__global__ void __launch_bounds__(256) prep_kernel(
    const float* __restrict__ x, const float* __restrict__ w03,
    const float* __restrict__ b03, const float* __restrict__ w01,
    const float* __restrict__ b01,
    const float* __restrict__ blW, const float* __restrict__ c2aw,
    const float* __restrict__ lp2w, const float* __restrict__ lp2b,
    int n, int nb_data)
{
    const int tid = threadIdx.x;
    if (blockIdx.x >= nb_data) {
        const int sb = blockIdx.x - nb_data;
        if (sb < 16) {
            const int id = sb * 256 + tid;
            const int o = id & 15;
            const int pr = id >> 4;
            const int jj = pr & 15;
            const int i = pr >> 4;
            float v;
            if (i < jj)       v = blW[o * 256 + i * 16 + jj] + blW[o * 256 + jj * 16 + i];
            else if (i == jj) v = blW[o * 256 + i * 16 + i];
            else              v = 0.f;
            g_blS[id] = v;
        } else {
            __shared__ float sM[48], s0[16];
            if (tid < 48) {
                const int r = tid >> 4, u = tid & 15;
                sM[tid] = lp2w[r * 64 + u] + lp2w[r * 64 + 16 + u] +
                          lp2w[r * 64 + 32 + u] + lp2w[r * 64 + 48 + u];
            }
            if (tid >= 48 && tid < 64) {
                const int u = tid - 48;
                s0[u] = lp2b[u] + lp2b[16 + u] + lp2b[32 + u] + lp2b[48 + u];
            }
            __syncthreads();
            if (tid < 192) {
                const int r = tid >> 6, c = tid & 63;
                float acc = 0.f;
#pragma unroll
                for (int u = 0; u < 16; u++)
                    acc += sM[r * 16 + u] * c2aw[(16 + u) * 64 + c];
                g_c2aQ[r * 64 + c] = acc;
            } else {
                const int c = tid - 192;
                float acc = 0.f;
#pragma unroll
                for (int u = 0; u < 16; u++)
                    acc += s0[u] * c2aw[(16 + u) * 64 + c];
                g_c2aC[c] = acc;
            }
        }
        return;
    }

    __shared__ float sw[4096];
    __shared__ float sw1[1024];
    __shared__ float sx[32][64];
    for (int i = tid; i < 1024; i += 256)
        ((float4*)sw)[i] = ((const float4*)w03)[i];
    for (int i = tid; i < 256; i += 256)
        ((float4*)sw1)[i] = ((const float4*)(w01 + 48))[i];
    const int base = blockIdx.x * 32;
    {
        const int c4 = tid & 15;
        const int r = tid >> 4;
#pragma unroll
        for (int a = 0; a < 2; a++) {
            const int row = base + r + a * 16;
            float4 v = make_float4(0.f, 0.f, 0.f, 0.f);
            if (row < n) v = ((const float4*)(x + (size_t)row * 64))[c4];
            ((float4*)sx[r + a * 16])[c4] = v;
        }
    }
    __syncthreads();

    {
        const int rq = tid >> 5;
        const int cp = tid & 31;
        const ull bcp = ((const ull*)b03)[cp];
        ull acc0 = bcp, acc1 = bcp, acc2 = bcp, acc3 = bcp;
#pragma unroll 8
        for (int d = 0; d < 64; d++) {
            const ull w2 = ((const ull*)(sw + d * 64))[cp];
            acc0 = fma2_(bc2(sx[rq * 4 + 0][d]), w2, acc0);
            acc1 = fma2_(bc2(sx[rq * 4 + 1][d]), w2, acc1);
            acc2 = fma2_(bc2(sx[rq * 4 + 2][d]), w2, acc2);
            acc3 = fma2_(bc2(sx[rq * 4 + 3][d]), w2, acc3);
        }
        const int r0 = base + rq * 4;
        if (r0 + 0 < n) ((ull*)(g_y + (size_t)(r0 + 0) * 64))[cp] = acc0;
        if (r0 + 1 < n) ((ull*)(g_y + (size_t)(r0 + 1) * 64))[cp] = acc1;
        if (r0 + 2 < n) ((ull*)(g_y + (size_t)(r0 + 2) * 64))[cp] = acc2;
        if (r0 + 3 < n) ((ull*)(g_y + (size_t)(r0 + 3) * 64))[cp] = acc3;
    }
    {
        const int r = tid >> 3;
        const int o8 = tid & 7;
        ull acc = ((const ull*)b01)[o8];
#pragma unroll 8
        for (int d = 0; d < 64; d++)
            acc = fma2_(bc2(sx[r][d]), ((const ull*)(sw1 + d * 16))[o8], acc);
        const int row = base + r;
        if (row < n) ((ull*)(g_hx + (size_t)row * 16))[o8] = acc;
    }
}

// ---------------------------------------------------------------------------
// Main kernel: 192 threads, P=3 point-slots per thread (36 points/block).
// ---------------------------------------------------------------------------
__global__ void __launch_bounds__(192, 2) pm_main_kernel(
    const float* __restrict__ p,
    const int* __restrict__ knn,
    const float* __restrict__ w01, const float* __restrict__ blB,
    const float* __restrict__ lp1w, const float* __restrict__ lp1b,
    const float* __restrict__ bnpg, const float* __restrict__ bnpb,
    const float* __restrict__ bnpm, const float* __restrict__ bnpv,
    const float* __restrict__ lp2w, const float* __restrict__ lp2b,
    const float* __restrict__ c2aw,
    const float* __restrict__ bn2ag, const float* __restrict__ bn2ab,
    const float* __restrict__ bn2am, const float* __restrict__ bn2av,
    const float* __restrict__ c2bw,
    const float* __restrict__ bn2bg, const float* __restrict__ bn2bb,
    const float* __restrict__ bn2bm, const float* __restrict__ bn2bv,
    const float* __restrict__ c2cw, const float* __restrict__ c2cb,
    float* __restrict__ out, float* __restrict__ xk_out,
    float* __restrict__ knn_out, float* __restrict__ pr_out,
    int n)
{
    __shared__ __align__(16) float s_blS[4096];
    __shared__ __align__(16) float s_c2a[1024];
    __shared__ __align__(16) float s_c2aQ[192];
    __shared__ __align__(16) float s_c2aC[64];
    __shared__ __align__(16) float s_c2b[512];
    __shared__ __align__(16) float s_c2c[64];
    __shared__ __align__(16) float s_lp2[192], s_lp2b[64];
    __shared__ __align__(16) float s_bn2as[64], s_bn2at[64];
    __shared__ __align__(16) float s_w01p[48];
    __shared__ __align__(16) float s_blB[16];
    __shared__ __align__(16) float s_lp1f[12], s_lp1c[4];
    __shared__ __align__(16) float s_bn2bs[8], s_bn2bt[8], s_c2cb[8];

    const int tid = threadIdx.x;

    // ---- staging ----
    for (int i = tid; i < 1024; i += 192)
        ((float4*)s_blS)[i] = ((const float4*)g_blS)[i];
    for (int i = tid; i < 256; i += 192)
        ((float4*)s_c2a)[i] = ((const float4*)c2aw)[i];
    for (int i = tid; i < 128; i += 192)
        ((float4*)s_c2b)[i] = ((const float4*)c2bw)[i];
    if (tid < 192) { s_c2aQ[tid] = g_c2aQ[tid]; s_lp2[tid] = lp2w[tid]; }
    if (tid < 64) {
        s_c2aC[tid] = g_c2aC[tid];
        s_lp2b[tid] = lp2b[tid];
        float sc = bn2ag[tid] * rsqrtf(bn2av[tid] + 1e-5f);
        s_bn2as[tid] = sc;
        s_bn2at[tid] = bn2ab[tid] - bn2am[tid] * sc;
        s_c2c[tid] = c2cw[tid];
    }
    if (tid < 48) s_w01p[tid] = w01[tid];
    if (tid < 16) s_blB[tid] = blB[tid];
    if (tid < 8) {
        float sc = bn2bg[tid] * rsqrtf(bn2bv[tid] + 1e-5f);
        s_bn2bs[tid] = sc;
        s_bn2bt[tid] = bn2bb[tid] - bn2bm[tid] * sc;
        s_c2cb[tid] = c2cb[tid];
    }
    if (tid < 3) {
        const int d = tid;
        float sc = bnpg[d] * rsqrtf(bnpv[d] + 1e-5f);
        s_lp1f[0 + d] = lp1w[0 * 3 + d] * sc;
        s_lp1f[4 + d] = lp1w[1 * 3 + d] * sc;
        s_lp1f[8 + d] = lp1w[2 * 3 + d] * sc;
        s_lp1c[d] = (lp1b[d] - bnpm[d]) * sc + bnpb[d];
    }
    __syncthreads();

    // ---- slot setup: warp = 2 k-halves of 16 lanes; 3 points per half ----
    const int k = tid & 15;
    const int half = (tid >> 4) & 1;
    const int wrp = tid >> 5;
    const int base = blockIdx.x * 36 + wrp * 6 + half * 3;

    int jS[3]; bool vS[3];
    float pr[3][3];
#pragma unroll
    for (int s = 0; s < 3; s++) {
        const int nn = base + s;
        const bool v = nn < n;
        const int nc = v ? nn : (n > 0 ? n - 1 : 0);
        const int j = knn[(size_t)nc * 16 + k];
        jS[s] = j; vS[s] = v;
        pr[s][0] = p[(size_t)j * 3 + 0] - p[(size_t)nc * 3 + 0];
        pr[s][1] = p[(size_t)j * 3 + 1] - p[(size_t)nc * 3 + 1];
        pr[s][2] = p[(size_t)j * 3 + 2] - p[(size_t)nc * 3 + 2];
        if (v && pr_out) {
            pr_out[((size_t)nn * 16 + k) * 3 + 0] = pr[s][0];
            pr_out[((size_t)nn * 16 + k) * 3 + 1] = pr[s][1];
            pr_out[((size_t)nn * 16 + k) * 3 + 2] = pr[s][2];
        }
        if (v && knn_out) knn_out[(size_t)nn * 16 + k] = (float)j;
    }

    // ---- h = relu(hx[j] + pr @ w01p) ----
    float h[3][16];
#pragma unroll
    for (int o4 = 0; o4 < 4; o4++) {
        float4 w0 = *(const float4*)(s_w01p + o4 * 4);
        float4 w1 = *(const float4*)(s_w01p + 16 + o4 * 4);
        float4 w2 = *(const float4*)(s_w01p + 32 + o4 * 4);
#pragma unroll
        for (int s = 0; s < 3; s++) {
            float4 a = ((const float4*)(g_hx + (size_t)jS[s] * 16))[o4];
            h[s][o4 * 4 + 0] = fmaxf(a.x + pr[s][0] * w0.x + pr[s][1] * w1.x + pr[s][2] * w2.x, 0.f);
            h[s][o4 * 4 + 1] = fmaxf(a.y + pr[s][0] * w0.y + pr[s][1] * w1.y + pr[s][2] * w2.y, 0.f);
            h[s][o4 * 4 + 2] = fmaxf(a.z + pr[s][0] * w0.z + pr[s][1] * w1.z + pr[s][2] * w2.z, 0.f);
            h[s][o4 * 4 + 3] = fmaxf(a.w + pr[s][0] * w0.w + pr[s][1] * w1.w + pr[s][2] * w2.w, 0.f);
        }
    }

    // ---- q = relu(BN(pr @ lp1)) ----
    float q[3][3];
#pragma unroll
    for (int s = 0; s < 3; s++)
#pragma unroll
        for (int d = 0; d < 3; d++)
            q[s][d] = fmaxf(fmaf(pr[s][0], s_lp1f[d],
                          fmaf(pr[s][1], s_lp1f[4 + d],
                          fmaf(pr[s][2], s_lp1f[8 + d], s_lp1c[d]))), 0.f);

    // ---- symmetrized bilinear, channel-packed, 3 slots ----
    ull ep[3][8];
    {
        const ull* bB = (const ull*)s_blB;
#pragma unroll
        for (int m = 0; m < 8; m++) {
            ull b = bB[m];
            ep[0][m] = b; ep[1][m] = b; ep[2][m] = b;
        }
    }
#pragma unroll
    for (int i = 0; i < 16; i++) {
#pragma unroll
        for (int jj = i; jj < 16; jj++) {
            const ull g0 = bc2(h[0][i] * h[0][jj]);
            const ull g1 = bc2(h[1][i] * h[1][jj]);
            const ull g2 = bc2(h[2][i] * h[2][jj]);
            const ulonglong2* wr = (const ulonglong2*)(s_blS + (i * 16 + jj) * 16);
            ulonglong2 w0 = wr[0], w1 = wr[1], w2 = wr[2], w3 = wr[3];
            ep[0][0] = fma2_(g0, w0.x, ep[0][0]); ep[0][1] = fma2_(g0, w0.y, ep[0][1]);
            ep[0][2] = fma2_(g0, w1.x, ep[0][2]); ep[0][3] = fma2_(g0, w1.y, ep[0][3]);
            ep[0][4] = fma2_(g0, w2.x, ep[0][4]); ep[0][5] = fma2_(g0, w2.y, ep[0][5]);
            ep[0][6] = fma2_(g0, w3.x, ep[0][6]); ep[0][7] = fma2_(g0, w3.y, ep[0][7]);
            ep[1][0] = fma2_(g1, w0.x, ep[1][0]); ep[1][1] = fma2_(g1, w0.y, ep[1][1]);
            ep[1][2] = fma2_(g1, w1.x, ep[1][2]); ep[1][3] = fma2_(g1, w1.y, ep[1][3]);
            ep[1][4] = fma2_(g1, w2.x, ep[1][4]); ep[1][5] = fma2_(g1, w2.y, ep[1][5]);
            ep[1][6] = fma2_(g1, w3.x, ep[1][6]); ep[1][7] = fma2_(g1, w3.y, ep[1][7]);
            ep[2][0] = fma2_(g2, w0.x, ep[2][0]); ep[2][1] = fma2_(g2, w0.y, ep[2][1]);
            ep[2][2] = fma2_(g2, w1.x, ep[2][2]); ep[2][3] = fma2_(g2, w1.y, ep[2][3]);
            ep[2][4] = fma2_(g2, w2.x, ep[2][4]); ep[2][5] = fma2_(g2, w2.y, ep[2][5]);
            ep[2][6] = fma2_(g2, w3.x, ep[2][6]); ep[2][7] = fma2_(g2, w3.y, ep[2][7]);
        }
    }

    // ---- fused c2a(+q)+BN+relu+c2b ----
    ull hb[3][4];
#pragma unroll
    for (int s = 0; s < 3; s++)
#pragma unroll
        for (int m = 0; m < 4; m++) hb[s][m] = 0ull;
#pragma unroll 1
    for (int cb = 0; cb < 4; cb++) {
        ull a[3][8];
        {
            const ulonglong2* ccp = (const ulonglong2*)(s_c2aC + cb * 16);
            ulonglong2 c0 = ccp[0], c1 = ccp[1], c2 = ccp[2], c3 = ccp[3];
            a[0][0] = c0.x; a[0][1] = c0.y; a[0][2] = c1.x; a[0][3] = c1.y;
            a[0][4] = c2.x; a[0][5] = c2.y; a[0][6] = c3.x; a[0][7] = c3.y;
#pragma unroll
            for (int m = 0; m < 8; m++) { a[1][m] = a[0][m]; a[2][m] = a[0][m]; }
        }
#pragma unroll
        for (int q8 = 0; q8 < 8; q8++) {
            float e0l, e0h, e1l, e1h, e2l, e2h;
            upk2(ep[0][q8], e0l, e0h);
            upk2(ep[1][q8], e1l, e1h);
            upk2(ep[2][q8], e2l, e2h);
#pragma unroll
            for (int hh = 0; hh < 2; hh++) {
                const ull v0 = bc2(hh ? e0h : e0l);
                const ull v1 = bc2(hh ? e1h : e1l);
                const ull v2 = bc2(hh ? e2h : e2l);
                const ulonglong2* wr = (const ulonglong2*)(s_c2a + (2 * q8 + hh) * 64 + cb * 16);
                ulonglong2 w0 = wr[0], w1 = wr[1], w2 = wr[2], w3 = wr[3];
                a[0][0] = fma2_(v0, w0.x, a[0][0]); a[0][1] = fma2_(v0, w0.y, a[0][1]);
                a[0][2] = fma2_(v0, w1.x, a[0][2]); a[0][3] = fma2_(v0, w1.y, a[0][3]);
                a[0][4] = fma2_(v0, w2.x, a[0][4]); a[0][5] = fma2_(v0, w2.y, a[0][5]);
                a[0][6] = fma2_(v0, w3.x, a[0][6]); a[0][7] = fma2_(v0, w3.y, a[0][7]);
                a[1][0] = fma2_(v1, w0.x, a[1][0]); a[1][1] = fma2_(v1, w0.y, a[1][1]);
                a[1][2] = fma2_(v1, w1.x, a[1][2]); a[1][3] = fma2_(v1, w1.y, a[1][3]);
                a[1][4] = fma2_(v1, w2.x, a[1][4]); a[1][5] = fma2_(v1, w2.y, a[1][5]);
                a[1][6] = fma2_(v1, w3.x, a[1][6]); a[1][7] = fma2_(v1, w3.y, a[1][7]);
                a[2][0] = fma2_(v2, w0.x, a[2][0]); a[2][1] = fma2_(v2, w0.y, a[2][1]);
                a[2][2] = fma2_(v2, w1.x, a[2][2]); a[2][3] = fma2_(v2, w1.y, a[2][3]);
                a[2][4] = fma2_(v2, w2.x, a[2][4]); a[2][5] = fma2_(v2, w2.y, a[2][5]);
                a[2][6] = fma2_(v2, w3.x, a[2][6]); a[2][7] = fma2_(v2, w3.y, a[2][7]);
            }
        }
#pragma unroll
        for (int r = 0; r < 3; r++) {
            const ull v0 = bc2(q[0][r]);
            const ull v1 = bc2(q[1][r]);
            const ull v2 = bc2(q[2][r]);
            const ulonglong2* wr = (const ulonglong2*)(s_c2aQ + r * 64 + cb * 16);
            ulonglong2 w0 = wr[0], w1 = wr[1], w2 = wr[2], w3 = wr[3];
            a[0][0] = fma2_(v0, w0.x, a[0][0]); a[0][1] = fma2_(v0, w0.y, a[0][1]);
            a[0][2] = fma2_(v0, w1.x, a[0][2]); a[0][3] = fma2_(v0, w1.y, a[0][3]);
            a[0][4] = fma2_(v0, w2.x, a[0][4]); a[0][5] = fma2_(v0, w2.y, a[0][5]);
            a[0][6] = fma2_(v0, w3.x, a[0][6]); a[0][7] = fma2_(v0, w3.y, a[0][7]);
            a[1][0] = fma2_(v1, w0.x, a[1][0]); a[1][1] = fma2_(v1, w0.y, a[1][1]);
            a[1][2] = fma2_(v1, w1.x, a[1][2]); a[1][3] = fma2_(v1, w1.y, a[1][3]);
            a[1][4] = fma2_(v1, w2.x, a[1][4]); a[1][5] = fma2_(v1, w2.y, a[1][5]);
            a[1][6] = fma2_(v1, w3.x, a[1][6]); a[1][7] = fma2_(v1, w3.y, a[1][7]);
            a[2][0] = fma2_(v2, w0.x, a[2][0]); a[2][1] = fma2_(v2, w0.y, a[2][1]);
            a[2][2] = fma2_(v2, w1.x, a[2][2]); a[2][3] = fma2_(v2, w1.y, a[2][3]);
            a[2][4] = fma2_(v2, w2.x, a[2][4]); a[2][5] = fma2_(v2, w2.y, a[2][5]);
            a[2][6] = fma2_(v2, w3.x, a[2][6]); a[2][7] = fma2_(v2, w3.y, a[2][7]);
        }
        // BN + relu + c2b
        const ull* scp = (const ull*)(s_bn2as + cb * 16);
        const ull* shp = (const ull*)(s_bn2at + cb * 16);
#pragma unroll
        for (int qq = 0; qq < 8; qq++) {
            float sc0, sc1, sh0, sh1;
            upk2(scp[qq], sc0, sc1); upk2(shp[qq], sh0, sh1);
            const ulonglong2* wb0 = (const ulonglong2*)(s_c2b + (cb * 16 + 2 * qq) * 8);
            const ulonglong2* wb1 = (const ulonglong2*)(s_c2b + (cb * 16 + 2 * qq + 1) * 8);
            ulonglong2 u0 = wb0[0], u1 = wb0[1];
            ulonglong2 u2 = wb1[0], u3 = wb1[1];
#pragma unroll
            for (int s = 0; s < 3; s++) {
                float vlo, vhi;
                upk2(a[s][qq], vlo, vhi);
                vlo = fmaxf(fmaf(vlo, sc0, sh0), 0.f);
                vhi = fmaxf(fmaf(vhi, sc1, sh1), 0.f);
                const ull bl = bc2(vlo), bh = bc2(vhi);
                hb[s][0] = fma2_(bl, u0.x, hb[s][0]); hb[s][1] = fma2_(bl, u0.y, hb[s][1]);
                hb[s][2] = fma2_(bl, u1.x, hb[s][2]); hb[s][3] = fma2_(bl, u1.y, hb[s][3]);
                hb[s][0] = fma2_(bh, u2.x, hb[s][0]); hb[s][1] = fma2_(bh, u2.y, hb[s][1]);
                hb[s][2] = fma2_(bh, u3.x, hb[s][2]); hb[s][3] = fma2_(bh, u3.y, hb[s][3]);
            }
        }
    }

    // ---- BN2b + relu, logits, softmax (no max pass; |logits| << 1) ----
    ull wsp[3][4];
#pragma unroll
    for (int s = 0; s < 3; s++) {
        float hbs[8];
#pragma unroll
        for (int m = 0; m < 4; m++) upk2(hb[s][m], hbs[2 * m], hbs[2 * m + 1]);
#pragma unroll
        for (int u = 0; u < 8; u++)
            hbs[u] = fmaxf(fmaf(hbs[u], s_bn2bs[u], s_bn2bt[u]), 0.f);

        ull lgp[4];
        {
            const ull* cbp = (const ull*)s_c2cb;
#pragma unroll
            for (int m = 0; m < 4; m++) lgp[m] = cbp[m];
        }
#pragma unroll
        for (int u = 0; u < 8; u++) {
            const ull hv = bc2(hbs[u]);
            const ulonglong2* wr = (const ulonglong2*)(s_c2c + u * 8);
            ulonglong2 w0 = wr[0], w1 = wr[1];
            lgp[0] = fma2_(hv, w0.x, lgp[0]); lgp[1] = fma2_(hv, w0.y, lgp[1]);
            lgp[2] = fma2_(hv, w1.x, lgp[2]); lgp[3] = fma2_(hv, w1.y, lgp[3]);
        }
        float ws[8];
#pragma unroll
        for (int m = 0; m < 4; m++) {
            float l0, l1;
            upk2(lgp[m], l0, l1);
            ws[2 * m] = __expf(l0);
            ws[2 * m + 1] = __expf(l1);
        }
#pragma unroll
        for (int c = 0; c < 8; c++) {
            float sm = ws[c];
#pragma unroll
            for (int d = 8; d > 0; d >>= 1)
                sm += __shfl_xor_sync(0xffffffffu, sm, d);
            ws[c] = __fdividef(ws[c], sm);
        }
#pragma unroll
        for (int m = 0; m < 4; m++) wsp[s][m] = pk2(ws[2 * m], ws[2 * m + 1]);
    }

    // ---- epilogue: xk = (y + pe) * w ; out = sum_k via shfl tree ----
    {
#pragma unroll
        for (int c4 = 0; c4 < 16; c4++) {
            ulonglong2 l0 = ((const ulonglong2*)s_lp2)[c4];
            ulonglong2 l1 = ((const ulonglong2*)(s_lp2 + 64))[c4];
            ulonglong2 l2 = ((const ulonglong2*)(s_lp2 + 128))[c4];
            ulonglong2 lb = ((const ulonglong2*)s_lp2b)[c4];
#pragma unroll
            for (int s = 0; s < 3; s++) {
                const ull q0 = bc2(q[s][0]), q1 = bc2(q[s][1]), q2 = bc2(q[s][2]);
                ulonglong2 y = ((const ulonglong2*)(g_y + (size_t)jS[s] * 64))[c4];
                ull pe = fma2_(q0, l0.x, fma2_(q1, l1.x, fma2_(q2, l2.x, lb.x)));
                ull vx = mul2_(add2_(y.x, pe), wsp[s][(2 * c4) & 3]);
                pe = fma2_(q0, l0.y, fma2_(q1, l1.y, fma2_(q2, l2.y, lb.y)));
                ull vy = mul2_(add2_(y.y, pe), wsp[s][(2 * c4 + 1) & 3]);
                if (vS[s] && xk_out) {
                    ulonglong2 t; t.x = vx; t.y = vy;
                    ((ulonglong2*)(xk_out + ((size_t)(base + s) * 16 + k) * 64))[c4] = t;
                }
#pragma unroll
                for (int d = 8; d > 0; d >>= 1) {
                    vx = add2_(vx, __shfl_down_sync(0xffffffffu, vx, d, 16));
                    vy = add2_(vy, __shfl_down_sync(0xffffffffu, vy, d, 16));
                }
                if (k == 0 && vS[s]) {
                    ulonglong2 t; t.x = vx; t.y = vy;
                    ((ulonglong2*)(out + (size_t)(base + s) * 64))[c4] = t;
                }
            }
        }
    }
}

// ---------------------------------------------------------------------------
extern "C" void kernel_launch(void* const* d_in, const int* in_sizes, int n_in,
                              void* d_out, int out_size)
{
    const float* p    = (const float*)d_in[0];
    const float* x    = (const float*)d_in[1];
    const int*   knn  = (const int*)d_in[2];
    const float* w01  = (const float*)d_in[3];
    const float* b01  = (const float*)d_in[4];
    const float* blW  = (const float*)d_in[5];
    const float* blB  = (const float*)d_in[6];
    const float* lp1w = (const float*)d_in[7];
    const float* lp1b = (const float*)d_in[8];
    const float* bnpg = (const float*)d_in[9];
    const float* bnpb = (const float*)d_in[10];
    const float* bnpm = (const float*)d_in[11];
    const float* bnpv = (const float*)d_in[12];
    const float* lp2w = (const float*)d_in[13];
    const float* lp2b = (const float*)d_in[14];
    const float* c2aw = (const float*)d_in[15];
    const float* bn2ag = (const float*)d_in[16];
    const float* bn2ab = (const float*)d_in[17];
    const float* bn2am = (const float*)d_in[18];
    const float* bn2av = (const float*)d_in[19];
    const float* c2bw  = (const float*)d_in[20];
    const float* bn2bg = (const float*)d_in[21];
    const float* bn2bb = (const float*)d_in[22];
    const float* bn2bm = (const float*)d_in[23];
    const float* bn2bv = (const float*)d_in[24];
    const float* c2cw  = (const float*)d_in[25];
    const float* c2cb  = (const float*)d_in[26];
    const float* w03   = (const float*)d_in[27];
    const float* b03   = (const float*)d_in[28];

    const int n = in_sizes[0] / 3;
    float* out = (float*)d_out;

    const long long total = (long long)n * 64 + (long long)n * 16 * 64 +
                            (long long)n * 16 + (long long)n * 16 * 3;
    float* xk_out = nullptr;
    float* knn_out = nullptr;
    float* pr_out = nullptr;
    if ((long long)out_size >= total) {
        xk_out  = out + (size_t)n * 64;
        knn_out = xk_out + (size_t)n * 16 * 64;
        pr_out  = knn_out + (size_t)n * 16;
    }

    const int nb_data = (n + 31) / 32;
    prep_kernel<<<nb_data + 17, 256>>>(x, w03, b03, w01, b01,
                                       blW, c2aw, lp2w, lp2b, n, nb_data);
    pm_main_kernel<<<(n + 35) / 36, 192>>>(p, knn, w01, blB,
                               lp1w, lp1b, bnpg, bnpb, bnpm, bnpv, lp2w, lp2b,
                               c2aw, bn2ag, bn2ab, bn2am, bn2av,
                               c2bw, bn2bg, bn2bb, bn2bm, bn2bv,
                               c2cw, c2cb,
                               out, xk_out, knn_out, pr_out, n);
}

// round 8
// speedup vs baseline: 1.6743x; 1.0676x over previous
#include <cuda_runtime.h>
#include <cstdint>

#define MAXN 100352

typedef unsigned long long ull;

__device__ float g_y[MAXN * 64];   // x @ w03 + b03
__device__ float g_hx[MAXN * 16];  // x @ w01[3:] + b01
__device__ float g_blS[4096];      // symmetrized bilinear [(i*16+jj)*16+o]
__device__ float g_c2aF[1024];     // c2a top half, BN2a-scale folded
__device__ float g_c2aQ[192];      // folded q->c2a, BN2a-scale folded
__device__ float g_c2aC[64];       // folded const->c2a, BN2a scale+shift folded
__device__ float g_c2bF[512];      // c2b, BN2b-scale folded

// ---- packed f32x2 helpers (FFMA2) ----
__device__ __forceinline__ ull pk2(float lo, float hi) {
    ull r; asm("mov.b64 %0,{%1,%2};" : "=l"(r) : "f"(lo), "f"(hi)); return r;
}
__device__ __forceinline__ ull bc2(float v) { return pk2(v, v); }
__device__ __forceinline__ void upk2(ull v, float& lo, float& hi) {
    asm("mov.b64 {%0,%1},%2;" : "=f"(lo), "=f"(hi) : "l"(v));
}
__device__ __forceinline__ ull fma2_(ull a, ull b, ull c) {
    ull d; asm("fma.rn.f32x2 %0,%1,%2,%3;" : "=l"(d) : "l"(a), "l"(b), "l"(c)); return d;
}
__device__ __forceinline__ ull add2_(ull a, ull b) {
    ull d; asm("add.rn.f32x2 %0,%1,%2;" : "=l"(d) : "l"(a), "l"(b)); return d;
}
__device__ __forceinline__ ull mul2_(ull a, ull b) {
    ull d; asm("mul.rn.f32x2 %0,%1,%2;" : "=l"(d) : "l"(a), "l"(b)); return d;
}

// ---------------------------------------------------------------------------
// Prep kernel: data blocks compute y & hx; 17 tail blocks do weight setup.
// ---------------------------------------------------------------------------
__global__ void __launch_bounds__(256) prep_kernel(
    const float* __restrict__ x, const float* __restrict__ w03,
    const float* __restrict__ b03, const float* __restrict__ w01,
    const float* __restrict__ b01,
    const float* __restrict__ blW, const float* __restrict__ c2aw,
    const float* __restrict__ lp2w, const float* __restrict__ lp2b,
    const float* __restrict__ bn2ag, const float* __restrict__ bn2ab,
    const float* __restrict__ bn2am, const float* __restrict__ bn2av,
    const float* __restrict__ c2bw, const float* __restrict__ bn2bg,
    const float* __restrict__ bn2bv,
    int n, int nb_data)
{
    const int tid = threadIdx.x;
    if (blockIdx.x >= nb_data) {
        const int sb = blockIdx.x - nb_data;
        if (sb < 16) {
            const int id = sb * 256 + tid;
            const int o = id & 15;
            const int pr = id >> 4;
            const int jj = pr & 15;
            const int i = pr >> 4;
            float v;
            if (i < jj)       v = blW[o * 256 + i * 16 + jj] + blW[o * 256 + jj * 16 + i];
            else if (i == jj) v = blW[o * 256 + i * 16 + i];
            else              v = 0.f;
            g_blS[id] = v;
        } else {
            __shared__ float sM[48], s0[16];
            __shared__ float sca[64], sha[64];
            if (tid < 48) {
                const int r = tid >> 4, u = tid & 15;
                sM[tid] = lp2w[r * 64 + u] + lp2w[r * 64 + 16 + u] +
                          lp2w[r * 64 + 32 + u] + lp2w[r * 64 + 48 + u];
            }
            if (tid >= 48 && tid < 64) {
                const int u = tid - 48;
                s0[u] = lp2b[u] + lp2b[16 + u] + lp2b[32 + u] + lp2b[48 + u];
            }
            if (tid >= 64 && tid < 128) {
                const int c = tid - 64;
                float sc = bn2ag[c] * rsqrtf(bn2av[c] + 1e-5f);
                sca[c] = sc;
                sha[c] = bn2ab[c] - bn2am[c] * sc;
            }
            __syncthreads();
            if (tid < 192) {
                const int r = tid >> 6, c = tid & 63;
                float acc = 0.f;
#pragma unroll
                for (int u = 0; u < 16; u++)
                    acc += sM[r * 16 + u] * c2aw[(16 + u) * 64 + c];
                g_c2aQ[r * 64 + c] = acc * sca[c];
            } else {
                const int c = tid - 192;
                float acc = 0.f;
#pragma unroll
                for (int u = 0; u < 16; u++)
                    acc += s0[u] * c2aw[(16 + u) * 64 + c];
                g_c2aC[c] = acc * sca[c] + sha[c];
            }
            // c2a top half with BN2a scale folded
#pragma unroll
            for (int t = 0; t < 4; t++) {
                const int i = tid + t * 256;
                g_c2aF[i] = c2aw[i] * sca[i & 63];
            }
            // c2b with BN2b scale folded
#pragma unroll
            for (int t = 0; t < 2; t++) {
                const int i = tid + t * 256;
                const int u = i & 7;
                g_c2bF[i] = c2bw[i] * (bn2bg[u] * rsqrtf(bn2bv[u] + 1e-5f));
            }
        }
        return;
    }

    __shared__ float sw[4096];
    __shared__ float sw1[1024];
    __shared__ float sx[32][64];
    for (int i = tid; i < 1024; i += 256)
        ((float4*)sw)[i] = ((const float4*)w03)[i];
    for (int i = tid; i < 256; i += 256)
        ((float4*)sw1)[i] = ((const float4*)(w01 + 48))[i];
    const int base = blockIdx.x * 32;
    {
        const int c4 = tid & 15;
        const int r = tid >> 4;
#pragma unroll
        for (int a = 0; a < 2; a++) {
            const int row = base + r + a * 16;
            float4 v = make_float4(0.f, 0.f, 0.f, 0.f);
            if (row < n) v = ((const float4*)(x + (size_t)row * 64))[c4];
            ((float4*)sx[r + a * 16])[c4] = v;
        }
    }
    __syncthreads();

    {
        const int rq = tid >> 5;
        const int cp = tid & 31;
        const ull bcp = ((const ull*)b03)[cp];
        ull acc0 = bcp, acc1 = bcp, acc2 = bcp, acc3 = bcp;
#pragma unroll 8
        for (int d = 0; d < 64; d++) {
            const ull w2 = ((const ull*)(sw + d * 64))[cp];
            acc0 = fma2_(bc2(sx[rq * 4 + 0][d]), w2, acc0);
            acc1 = fma2_(bc2(sx[rq * 4 + 1][d]), w2, acc1);
            acc2 = fma2_(bc2(sx[rq * 4 + 2][d]), w2, acc2);
            acc3 = fma2_(bc2(sx[rq * 4 + 3][d]), w2, acc3);
        }
        const int r0 = base + rq * 4;
        if (r0 + 0 < n) ((ull*)(g_y + (size_t)(r0 + 0) * 64))[cp] = acc0;
        if (r0 + 1 < n) ((ull*)(g_y + (size_t)(r0 + 1) * 64))[cp] = acc1;
        if (r0 + 2 < n) ((ull*)(g_y + (size_t)(r0 + 2) * 64))[cp] = acc2;
        if (r0 + 3 < n) ((ull*)(g_y + (size_t)(r0 + 3) * 64))[cp] = acc3;
    }
    {
        const int r = tid >> 3;
        const int o8 = tid & 7;
        ull acc = ((const ull*)b01)[o8];
#pragma unroll 8
        for (int d = 0; d < 64; d++)
            acc = fma2_(bc2(sx[r][d]), ((const ull*)(sw1 + d * 16))[o8], acc);
        const int row = base + r;
        if (row < n) ((ull*)(g_hx + (size_t)row * 16))[o8] = acc;
    }
}

// ---------------------------------------------------------------------------
// Main kernel: 256 threads, P=2 point-slots per thread (32 points/block).
// ---------------------------------------------------------------------------
__global__ void __launch_bounds__(256, 2) pm_main_kernel(
    const float* __restrict__ p,
    const int* __restrict__ knn,
    const float* __restrict__ w01, const float* __restrict__ blB,
    const float* __restrict__ lp1w, const float* __restrict__ lp1b,
    const float* __restrict__ bnpg, const float* __restrict__ bnpb,
    const float* __restrict__ bnpm, const float* __restrict__ bnpv,
    const float* __restrict__ lp2w, const float* __restrict__ lp2b,
    const float* __restrict__ bn2bg, const float* __restrict__ bn2bb,
    const float* __restrict__ bn2bm, const float* __restrict__ bn2bv,
    const float* __restrict__ c2cw, const float* __restrict__ c2cb,
    float* __restrict__ out, float* __restrict__ xk_out,
    float* __restrict__ knn_out, float* __restrict__ pr_out,
    int n)
{
    __shared__ __align__(16) float s_blS[4096];
    __shared__ __align__(16) float s_c2a[1024];
    __shared__ __align__(16) float s_c2aQ[192];
    __shared__ __align__(16) float s_c2aC[64];
    __shared__ __align__(16) float s_c2b[512];
    __shared__ __align__(16) float s_c2c[64];
    __shared__ __align__(16) float s_lp2[192], s_lp2b[64];
    __shared__ __align__(16) float s_w01p[48];
    __shared__ __align__(16) float s_blB[16];
    __shared__ __align__(16) float s_lp1f[12], s_lp1c[4];
    __shared__ __align__(16) float s_bn2bt[8], s_c2cb[8];

    const int tid = threadIdx.x;

    // ---- staging (all linear) ----
#pragma unroll
    for (int i = 0; i < 4; i++)
        ((float4*)s_blS)[tid + i * 256] = ((const float4*)g_blS)[tid + i * 256];
    ((float4*)s_c2a)[tid] = ((const float4*)g_c2aF)[tid];
    if (tid < 128) ((float4*)s_c2b)[tid] = ((const float4*)g_c2bF)[tid];
    if (tid < 192) { s_c2aQ[tid] = g_c2aQ[tid]; s_lp2[tid] = lp2w[tid]; }
    if (tid < 64) {
        s_c2aC[tid] = g_c2aC[tid];
        s_lp2b[tid] = lp2b[tid];
        s_c2c[tid] = c2cw[tid];
    }
    if (tid < 48) s_w01p[tid] = w01[tid];
    if (tid < 16) s_blB[tid] = blB[tid];
    if (tid < 8) {
        float sc = bn2bg[tid] * rsqrtf(bn2bv[tid] + 1e-5f);
        s_bn2bt[tid] = bn2bb[tid] - bn2bm[tid] * sc;
        s_c2cb[tid] = c2cb[tid];
    }
    if (tid < 3) {
        const int d = tid;
        float sc = bnpg[d] * rsqrtf(bnpv[d] + 1e-5f);
        s_lp1f[0 + d] = lp1w[0 * 3 + d] * sc;
        s_lp1f[4 + d] = lp1w[1 * 3 + d] * sc;
        s_lp1f[8 + d] = lp1w[2 * 3 + d] * sc;
        s_lp1c[d] = (lp1b[d] - bnpm[d]) * sc + bnpb[d];
    }
    __syncthreads();

    // ---- pair setup ----
    const int k = tid & 15;
    const int half = (tid >> 4) & 1;
    const int wrp = tid >> 5;
    const int base = blockIdx.x * 32 + wrp * 4 + half * 2;
    const int nn0 = base, nn1 = base + 1;
    const bool v0 = nn0 < n, v1 = nn1 < n;
    const int nc0 = v0 ? nn0 : (n > 0 ? n - 1 : 0);
    const int nc1 = v1 ? nn1 : (n > 0 ? n - 1 : 0);
    const int j0 = knn[(size_t)nc0 * 16 + k];
    const int j1 = knn[(size_t)nc1 * 16 + k];

    const float pA0 = p[(size_t)j0 * 3 + 0] - p[(size_t)nc0 * 3 + 0];
    const float pA1 = p[(size_t)j0 * 3 + 1] - p[(size_t)nc0 * 3 + 1];
    const float pA2 = p[(size_t)j0 * 3 + 2] - p[(size_t)nc0 * 3 + 2];
    const float pB0 = p[(size_t)j1 * 3 + 0] - p[(size_t)nc1 * 3 + 0];
    const float pB1 = p[(size_t)j1 * 3 + 1] - p[(size_t)nc1 * 3 + 1];
    const float pB2 = p[(size_t)j1 * 3 + 2] - p[(size_t)nc1 * 3 + 2];
    if (v0 && pr_out) {
        pr_out[((size_t)nn0 * 16 + k) * 3 + 0] = pA0;
        pr_out[((size_t)nn0 * 16 + k) * 3 + 1] = pA1;
        pr_out[((size_t)nn0 * 16 + k) * 3 + 2] = pA2;
    }
    if (v1 && pr_out) {
        pr_out[((size_t)nn1 * 16 + k) * 3 + 0] = pB0;
        pr_out[((size_t)nn1 * 16 + k) * 3 + 1] = pB1;
        pr_out[((size_t)nn1 * 16 + k) * 3 + 2] = pB2;
    }
    if (v0 && knn_out) knn_out[(size_t)nn0 * 16 + k] = (float)j0;
    if (v1 && knn_out) knn_out[(size_t)nn1 * 16 + k] = (float)j1;

    // ---- h = relu(hx[j] + pr @ w01p) ----
    float h0[16], h1[16];
    {
        const float4* hxa = (const float4*)(g_hx + (size_t)j0 * 16);
        const float4* hxb = (const float4*)(g_hx + (size_t)j1 * 16);
#pragma unroll
        for (int o4 = 0; o4 < 4; o4++) {
            float4 a = hxa[o4], b = hxb[o4];
            float4 w0 = *(const float4*)(s_w01p + o4 * 4);
            float4 w1 = *(const float4*)(s_w01p + 16 + o4 * 4);
            float4 w2 = *(const float4*)(s_w01p + 32 + o4 * 4);
            h0[o4 * 4 + 0] = fmaxf(a.x + pA0 * w0.x + pA1 * w1.x + pA2 * w2.x, 0.f);
            h0[o4 * 4 + 1] = fmaxf(a.y + pA0 * w0.y + pA1 * w1.y + pA2 * w2.y, 0.f);
            h0[o4 * 4 + 2] = fmaxf(a.z + pA0 * w0.z + pA1 * w1.z + pA2 * w2.z, 0.f);
            h0[o4 * 4 + 3] = fmaxf(a.w + pA0 * w0.w + pA1 * w1.w + pA2 * w2.w, 0.f);
            h1[o4 * 4 + 0] = fmaxf(b.x + pB0 * w0.x + pB1 * w1.x + pB2 * w2.x, 0.f);
            h1[o4 * 4 + 1] = fmaxf(b.y + pB0 * w0.y + pB1 * w1.y + pB2 * w2.y, 0.f);
            h1[o4 * 4 + 2] = fmaxf(b.z + pB0 * w0.z + pB1 * w1.z + pB2 * w2.z, 0.f);
            h1[o4 * 4 + 3] = fmaxf(b.w + pB0 * w0.w + pB1 * w1.w + pB2 * w2.w, 0.f);
        }
    }

    // ---- symmetrized bilinear, packed over o-pairs ----
    ull e0p[8], e1p[8];
    {
        const ull* bB = (const ull*)s_blB;
#pragma unroll
        for (int q = 0; q < 8; q++) { ull b = bB[q]; e0p[q] = b; e1p[q] = b; }
    }
#pragma unroll
    for (int i = 0; i < 16; i++) {
#pragma unroll
        for (int jj = i; jj < 16; jj++) {
            const ull ga2 = bc2(h0[i] * h0[jj]);
            const ull gb2 = bc2(h1[i] * h1[jj]);
            const ulonglong2* wr = (const ulonglong2*)(s_blS + (i * 16 + jj) * 16);
            ulonglong2 w0 = wr[0], w1 = wr[1], w2 = wr[2], w3 = wr[3];
            e0p[0] = fma2_(ga2, w0.x, e0p[0]); e1p[0] = fma2_(gb2, w0.x, e1p[0]);
            e0p[1] = fma2_(ga2, w0.y, e0p[1]); e1p[1] = fma2_(gb2, w0.y, e1p[1]);
            e0p[2] = fma2_(ga2, w1.x, e0p[2]); e1p[2] = fma2_(gb2, w1.x, e1p[2]);
            e0p[3] = fma2_(ga2, w1.y, e0p[3]); e1p[3] = fma2_(gb2, w1.y, e1p[3]);
            e0p[4] = fma2_(ga2, w2.x, e0p[4]); e1p[4] = fma2_(gb2, w2.x, e1p[4]);
            e0p[5] = fma2_(ga2, w2.y, e0p[5]); e1p[5] = fma2_(gb2, w2.y, e1p[5]);
            e0p[6] = fma2_(ga2, w3.x, e0p[6]); e1p[6] = fma2_(gb2, w3.x, e1p[6]);
            e0p[7] = fma2_(ga2, w3.y, e0p[7]); e1p[7] = fma2_(gb2, w3.y, e1p[7]);
        }
    }

    // ---- q vec ----
    float qa[3], qb[3];
#pragma unroll
    for (int d = 0; d < 3; d++) {
        qa[d] = fmaxf(fmaf(pA0, s_lp1f[d], fmaf(pA1, s_lp1f[4 + d], fmaf(pA2, s_lp1f[8 + d], s_lp1c[d]))), 0.f);
        qb[d] = fmaxf(fmaf(pB0, s_lp1f[d], fmaf(pB1, s_lp1f[4 + d], fmaf(pB2, s_lp1f[8 + d], s_lp1c[d]))), 0.f);
    }

    // ---- fused c2a(+q, BN folded)+relu+c2b(BN-scale folded) ----
    ull hb0p[4], hb1p[4];
    {
        const ull* shb = (const ull*)s_bn2bt;
#pragma unroll
        for (int m = 0; m < 4; m++) { ull b = shb[m]; hb0p[m] = b; hb1p[m] = b; }
    }
#pragma unroll
    for (int cb = 0; cb < 4; cb++) {
        ull a0p[8], a1p[8];
        {
            const ulonglong2* ccp = (const ulonglong2*)(s_c2aC + cb * 16);
            ulonglong2 c0 = ccp[0], c1 = ccp[1], c2 = ccp[2], c3 = ccp[3];
            a0p[0] = c0.x; a0p[1] = c0.y; a0p[2] = c1.x; a0p[3] = c1.y;
            a0p[4] = c2.x; a0p[5] = c2.y; a0p[6] = c3.x; a0p[7] = c3.y;
#pragma unroll
            for (int q = 0; q < 8; q++) a1p[q] = a0p[q];
        }
#pragma unroll
        for (int q8 = 0; q8 < 8; q8++) {
            float e0lo, e0hi, e1lo, e1hi;
            upk2(e0p[q8], e0lo, e0hi);
            upk2(e1p[q8], e1lo, e1hi);
#pragma unroll
            for (int hh = 0; hh < 2; hh++) {
                const ull va2 = bc2(hh ? e0hi : e0lo);
                const ull vb2 = bc2(hh ? e1hi : e1lo);
                const ulonglong2* wr = (const ulonglong2*)(s_c2a + (2 * q8 + hh) * 64 + cb * 16);
                ulonglong2 w0 = wr[0], w1 = wr[1], w2 = wr[2], w3 = wr[3];
                a0p[0] = fma2_(va2, w0.x, a0p[0]); a1p[0] = fma2_(vb2, w0.x, a1p[0]);
                a0p[1] = fma2_(va2, w0.y, a0p[1]); a1p[1] = fma2_(vb2, w0.y, a1p[1]);
                a0p[2] = fma2_(va2, w1.x, a0p[2]); a1p[2] = fma2_(vb2, w1.x, a1p[2]);
                a0p[3] = fma2_(va2, w1.y, a0p[3]); a1p[3] = fma2_(vb2, w1.y, a1p[3]);
                a0p[4] = fma2_(va2, w2.x, a0p[4]); a1p[4] = fma2_(vb2, w2.x, a1p[4]);
                a0p[5] = fma2_(va2, w2.y, a0p[5]); a1p[5] = fma2_(vb2, w2.y, a1p[5]);
                a0p[6] = fma2_(va2, w3.x, a0p[6]); a1p[6] = fma2_(vb2, w3.x, a1p[6]);
                a0p[7] = fma2_(va2, w3.y, a0p[7]); a1p[7] = fma2_(vb2, w3.y, a1p[7]);
            }
        }
#pragma unroll
        for (int r = 0; r < 3; r++) {
            const ull va2 = bc2(qa[r]);
            const ull vb2 = bc2(qb[r]);
            const ulonglong2* wr = (const ulonglong2*)(s_c2aQ + r * 64 + cb * 16);
            ulonglong2 w0 = wr[0], w1 = wr[1], w2 = wr[2], w3 = wr[3];
            a0p[0] = fma2_(va2, w0.x, a0p[0]); a1p[0] = fma2_(vb2, w0.x, a1p[0]);
            a0p[1] = fma2_(va2, w0.y, a0p[1]); a1p[1] = fma2_(vb2, w0.y, a1p[1]);
            a0p[2] = fma2_(va2, w1.x, a0p[2]); a1p[2] = fma2_(vb2, w1.x, a1p[2]);
            a0p[3] = fma2_(va2, w1.y, a0p[3]); a1p[3] = fma2_(vb2, w1.y, a1p[3]);
            a0p[4] = fma2_(va2, w2.x, a0p[4]); a1p[4] = fma2_(vb2, w2.x, a1p[4]);
            a0p[5] = fma2_(va2, w2.y, a0p[5]); a1p[5] = fma2_(vb2, w2.y, a1p[5]);
            a0p[6] = fma2_(va2, w3.x, a0p[6]); a1p[6] = fma2_(vb2, w3.x, a1p[6]);
            a0p[7] = fma2_(va2, w3.y, a0p[7]); a1p[7] = fma2_(vb2, w3.y, a1p[7]);
        }
        // relu (BN already folded) + c2b (scale folded)
#pragma unroll
        for (int q = 0; q < 8; q++) {
            float v00, v01, v10, v11;
            upk2(a0p[q], v00, v01); upk2(a1p[q], v10, v11);
            v00 = fmaxf(v00, 0.f);
            v01 = fmaxf(v01, 0.f);
            v10 = fmaxf(v10, 0.f);
            v11 = fmaxf(v11, 0.f);
            const ulonglong2* wb0 = (const ulonglong2*)(s_c2b + (cb * 16 + 2 * q) * 8);
            const ulonglong2* wb1 = (const ulonglong2*)(s_c2b + (cb * 16 + 2 * q + 1) * 8);
            ulonglong2 u0 = wb0[0], u1 = wb0[1];
            ulonglong2 u2 = wb1[0], u3 = wb1[1];
            const ull va2 = bc2(v00), vA2 = bc2(v01);
            const ull vb2 = bc2(v10), vB2 = bc2(v11);
            hb0p[0] = fma2_(va2, u0.x, hb0p[0]); hb0p[1] = fma2_(va2, u0.y, hb0p[1]);
            hb0p[2] = fma2_(va2, u1.x, hb0p[2]); hb0p[3] = fma2_(va2, u1.y, hb0p[3]);
            hb0p[0] = fma2_(vA2, u2.x, hb0p[0]); hb0p[1] = fma2_(vA2, u2.y, hb0p[1]);
            hb0p[2] = fma2_(vA2, u3.x, hb0p[2]); hb0p[3] = fma2_(vA2, u3.y, hb0p[3]);
            hb1p[0] = fma2_(vb2, u0.x, hb1p[0]); hb1p[1] = fma2_(vb2, u0.y, hb1p[1]);
            hb1p[2] = fma2_(vb2, u1.x, hb1p[2]); hb1p[3] = fma2_(vb2, u1.y, hb1p[3]);
            hb1p[0] = fma2_(vB2, u2.x, hb1p[0]); hb1p[1] = fma2_(vB2, u2.y, hb1p[1]);
            hb1p[2] = fma2_(vB2, u3.x, hb1p[2]); hb1p[3] = fma2_(vB2, u3.y, hb1p[3]);
        }
    }
    float hbs0[8], hbs1[8];
#pragma unroll
    for (int m = 0; m < 4; m++) {
        upk2(hb0p[m], hbs0[2 * m], hbs0[2 * m + 1]);
        upk2(hb1p[m], hbs1[2 * m], hbs1[2 * m + 1]);
    }
#pragma unroll
    for (int u = 0; u < 8; u++) {
        hbs0[u] = fmaxf(hbs0[u], 0.f);
        hbs1[u] = fmaxf(hbs1[u], 0.f);
    }

    // ---- logits (packed) ----
    ull lg0p[4], lg1p[4];
    {
        const ull* cbp = (const ull*)s_c2cb;
#pragma unroll
        for (int m = 0; m < 4; m++) { ull b = cbp[m]; lg0p[m] = b; lg1p[m] = b; }
    }
#pragma unroll
    for (int u = 0; u < 8; u++) {
        const ull h02 = bc2(hbs0[u]);
        const ull h12 = bc2(hbs1[u]);
        const ulonglong2* wr = (const ulonglong2*)(s_c2c + u * 8);
        ulonglong2 w0 = wr[0], w1 = wr[1];
        lg0p[0] = fma2_(h02, w0.x, lg0p[0]); lg1p[0] = fma2_(h12, w0.x, lg1p[0]);
        lg0p[1] = fma2_(h02, w0.y, lg0p[1]); lg1p[1] = fma2_(h12, w0.y, lg1p[1]);
        lg0p[2] = fma2_(h02, w1.x, lg0p[2]); lg1p[2] = fma2_(h12, w1.x, lg1p[2]);
        lg0p[3] = fma2_(h02, w1.y, lg0p[3]); lg1p[3] = fma2_(h12, w1.y, lg1p[3]);
    }

    // ---- softmax over 16 k-lanes (no max pass; |logits| << 1) ----
    float ws0[8], ws1[8];
#pragma unroll
    for (int m = 0; m < 4; m++) {
        float l0, l1;
        upk2(lg0p[m], l0, l1);
        ws0[2 * m] = __expf(l0); ws0[2 * m + 1] = __expf(l1);
        upk2(lg1p[m], l0, l1);
        ws1[2 * m] = __expf(l0); ws1[2 * m + 1] = __expf(l1);
    }
#pragma unroll
    for (int c = 0; c < 8; c++) {
        float s0 = ws0[c], s1 = ws1[c];
#pragma unroll
        for (int d = 8; d > 0; d >>= 1) {
            s0 += __shfl_xor_sync(0xffffffffu, s0, d);
            s1 += __shfl_xor_sync(0xffffffffu, s1, d);
        }
        ws0[c] = __fdividef(ws0[c], s0);
        ws1[c] = __fdividef(ws1[c], s1);
    }
    ull ws0p[4], ws1p[4];
#pragma unroll
    for (int m = 0; m < 4; m++) {
        ws0p[m] = pk2(ws0[2 * m], ws0[2 * m + 1]);
        ws1p[m] = pk2(ws1[2 * m], ws1[2 * m + 1]);
    }

    // ---- epilogue (packed): xk = (y + pe) * w ; out = sum_k ----
    {
        const float* yr0 = g_y + (size_t)j0 * 64;
        const float* yr1 = g_y + (size_t)j1 * 64;
        float* xp0 = (v0 && xk_out) ? (xk_out + ((size_t)nn0 * 16 + k) * 64) : nullptr;
        float* xp1 = (v1 && xk_out) ? (xk_out + ((size_t)nn1 * 16 + k) * 64) : nullptr;
        const ull qa0 = bc2(qa[0]), qa1 = bc2(qa[1]), qa2v = bc2(qa[2]);
        const ull qb0 = bc2(qb[0]), qb1 = bc2(qb[1]), qb2v = bc2(qb[2]);
#pragma unroll
        for (int c4 = 0; c4 < 16; c4++) {
            ulonglong2 l0 = ((const ulonglong2*)s_lp2)[c4];
            ulonglong2 l1 = ((const ulonglong2*)(s_lp2 + 64))[c4];
            ulonglong2 l2 = ((const ulonglong2*)(s_lp2 + 128))[c4];
            ulonglong2 lb = ((const ulonglong2*)s_lp2b)[c4];
            ulonglong2 y0 = ((const ulonglong2*)yr0)[c4];
            ulonglong2 y1 = ((const ulonglong2*)yr1)[c4];
            const ull wA0 = ws0p[(2 * c4) & 3], wA1 = ws0p[(2 * c4 + 1) & 3];
            const ull wB0 = ws1p[(2 * c4) & 3], wB1 = ws1p[(2 * c4 + 1) & 3];
            ull pe;
            pe = fma2_(qa0, l0.x, fma2_(qa1, l1.x, fma2_(qa2v, l2.x, lb.x)));
            ull v0x = mul2_(add2_(y0.x, pe), wA0);
            pe = fma2_(qa0, l0.y, fma2_(qa1, l1.y, fma2_(qa2v, l2.y, lb.y)));
            ull v0y = mul2_(add2_(y0.y, pe), wA1);
            pe = fma2_(qb0, l0.x, fma2_(qb1, l1.x, fma2_(qb2v, l2.x, lb.x)));
            ull v1x = mul2_(add2_(y1.x, pe), wB0);
            pe = fma2_(qb0, l0.y, fma2_(qb1, l1.y, fma2_(qb2v, l2.y, lb.y)));
            ull v1y = mul2_(add2_(y1.y, pe), wB1);
            if (xp0) { ulonglong2 t; t.x = v0x; t.y = v0y; ((ulonglong2*)xp0)[c4] = t; }
            if (xp1) { ulonglong2 t; t.x = v1x; t.y = v1y; ((ulonglong2*)xp1)[c4] = t; }
#pragma unroll
            for (int d = 8; d > 0; d >>= 1) {
                v0x = add2_(v0x, __shfl_down_sync(0xffffffffu, v0x, d, 16));
                v0y = add2_(v0y, __shfl_down_sync(0xffffffffu, v0y, d, 16));
                v1x = add2_(v1x, __shfl_down_sync(0xffffffffu, v1x, d, 16));
                v1y = add2_(v1y, __shfl_down_sync(0xffffffffu, v1y, d, 16));
            }
            if (k == 0) {
                if (v0) { ulonglong2 t; t.x = v0x; t.y = v0y; ((ulonglong2*)(out + (size_t)nn0 * 64))[c4] = t; }
                if (v1) { ulonglong2 t; t.x = v1x; t.y = v1y; ((ulonglong2*)(out + (size_t)nn1 * 64))[c4] = t; }
            }
        }
    }
}

// ---------------------------------------------------------------------------
extern "C" void kernel_launch(void* const* d_in, const int* in_sizes, int n_in,
                              void* d_out, int out_size)
{
    const float* p    = (const float*)d_in[0];
    const float* x    = (const float*)d_in[1];
    const int*   knn  = (const int*)d_in[2];
    const float* w01  = (const float*)d_in[3];
    const float* b01  = (const float*)d_in[4];
    const float* blW  = (const float*)d_in[5];
    const float* blB  = (const float*)d_in[6];
    const float* lp1w = (const float*)d_in[7];
    const float* lp1b = (const float*)d_in[8];
    const float* bnpg = (const float*)d_in[9];
    const float* bnpb = (const float*)d_in[10];
    const float* bnpm = (const float*)d_in[11];
    const float* bnpv = (const float*)d_in[12];
    const float* lp2w = (const float*)d_in[13];
    const float* lp2b = (const float*)d_in[14];
    const float* c2aw = (const float*)d_in[15];
    const float* bn2ag = (const float*)d_in[16];
    const float* bn2ab = (const float*)d_in[17];
    const float* bn2am = (const float*)d_in[18];
    const float* bn2av = (const float*)d_in[19];
    const float* c2bw  = (const float*)d_in[20];
    const float* bn2bg = (const float*)d_in[21];
    const float* bn2bb = (const float*)d_in[22];
    const float* bn2bm = (const float*)d_in[23];
    const float* bn2bv = (const float*)d_in[24];
    const float* c2cw  = (const float*)d_in[25];
    const float* c2cb  = (const float*)d_in[26];
    const float* w03   = (const float*)d_in[27];
    const float* b03   = (const float*)d_in[28];

    const int n = in_sizes[0] / 3;
    float* out = (float*)d_out;

    const long long total = (long long)n * 64 + (long long)n * 16 * 64 +
                            (long long)n * 16 + (long long)n * 16 * 3;
    float* xk_out = nullptr;
    float* knn_out = nullptr;
    float* pr_out = nullptr;
    if ((long long)out_size >= total) {
        xk_out  = out + (size_t)n * 64;
        knn_out = xk_out + (size_t)n * 16 * 64;
        pr_out  = knn_out + (size_t)n * 16;
    }

    const int nb_data = (n + 31) / 32;
    prep_kernel<<<nb_data + 17, 256>>>(x, w03, b03, w01, b01,
                                       blW, c2aw, lp2w, lp2b,
                                       bn2ag, bn2ab, bn2am, bn2av,
                                       c2bw, bn2bg, bn2bv, n, nb_data);
    pm_main_kernel<<<(n + 31) / 32, 256>>>(p, knn, w01, blB,
                               lp1w, lp1b, bnpg, bnpb, bnpm, bnpv, lp2w, lp2b,
                               bn2bg, bn2bb, bn2bm, bn2bv,
                               c2cw, c2cb,
                               out, xk_out, knn_out, pr_out, n);
}